// round 6
// baseline (speedup 1.0000x reference)
#include <cuda_runtime.h>
#include <cuda_bf16.h>
#include <cstdint>

// Folded table in GLOBAL memory (i-independent, built once by a pre-kernel):
//   rows   0..4  : C[c] = W[65] + W[131] + W[133+c]   (diff chain, HOT: ~98.4% of pairs)
//   row    5     : W[132]                             (entity row)
//   rows   6..70 : A[r] = W[r] + W[131] + W[138]      (same chain, dres!=0)
//   rows  71..135: B[t] = W[32] + W[66+t] + W[138]    (same chain, dres==0)
// Main kernel: 128 thr x 12 blocks/SM (single wave), warp handles 4 consecutive
// j rows per iteration (int4 index broadcast, 2KB contiguous store span, 4-deep MLP).

#define TAB_ROWS 136

__device__ float g_table[TAB_ROWS * 128];

__global__ void build_table(const float* __restrict__ W)
{
    const int idx = blockIdx.x * blockDim.x + threadIdx.x;
    if (idx >= TAB_ROWS * 128) return;
    const int r = idx >> 7;
    const int e = idx & 127;
    float v;
    if (r < 5) {
        v = W[65 * 128 + e] + W[131 * 128 + e] + W[(133 + r) * 128 + e];
    } else if (r == 5) {
        v = W[132 * 128 + e];
    } else if (r < 71) {
        v = W[(r - 6) * 128 + e] + W[131 * 128 + e] + W[138 * 128 + e];
    } else {
        v = W[32 * 128 + e] + W[(66 + (r - 71)) * 128 + e] + W[138 * 128 + e];
    }
    g_table[idx] = v;
}

__global__ void __launch_bounds__(128, 12)
rpe_main(const float* __restrict__ feats, float* __restrict__ out, int n)
{
    __shared__ int jidx[1024];

    const int tid = threadIdx.x;
    const int i   = blockIdx.x;

    // ---- Phase A: per-j packed index (row | ent<<8) ----
    const float res_i  = feats[i * 10 + 0];
    const float tok_i  = feats[i * 10 + 1];
    const float asym_i = feats[i * 10 + 2];
    const float ent_i  = feats[i * 10 + 3];
    const float sym_i  = feats[i * 10 + 4];

    for (int j = tid; j < n; j += blockDim.x) {
        const float res_j  = feats[j * 10 + 0];
        const float tok_j  = feats[j * 10 + 1];
        const float asym_j = feats[j * 10 + 2];
        const float ent_j  = feats[j * 10 + 3];
        const float sym_j  = feats[j * 10 + 4];

        int row;
        if (asym_i == asym_j) {
            const int dres = (int)(res_i - res_j);
            if (dres != 0) {
                row = 6 + min(max(dres + 32, 0), 64);          // A table
            } else {
                const int dtok = (int)(tok_i - tok_j);
                row = 71 + min(max(dtok + 32, 0), 64);         // B table
            }
        } else {
            row = min(max((int)(sym_i - sym_j) + 2, 0), 4);    // C table (hot)
        }
        const int ent = (ent_i == ent_j) ? 1 : 0;
        jidx[j] = row | (ent << 8);
    }
    __syncthreads();

    // ---- Phase B: 4 consecutive j rows per warp-iteration ----
    const int e4  = tid & 31;                    // float4 lane within 128-dim row
    const int wid = tid >> 5;                    // 4 warps
    const float4* __restrict__ T4 = (const float4*)g_table;
    const int4*   __restrict__ J4 = (const int4*)jidx;

    const float4 went = __ldg(&T4[5 * 32 + e4]); // entity row in registers

    float* __restrict__ out_i = out + ((size_t)i * (size_t)n) * 128;
    const int nb4 = n >> 2;                      // 256 groups of 4 j's

    for (int jb = wid; jb < nb4; jb += 4) {
        const int4 p = J4[jb];                   // one LDS.128 broadcast = 4 indices

        float4 v0 = __ldg(&T4[(p.x & 255) * 32 + e4]);
        float4 v1 = __ldg(&T4[(p.y & 255) * 32 + e4]);
        float4 v2 = __ldg(&T4[(p.z & 255) * 32 + e4]);
        float4 v3 = __ldg(&T4[(p.w & 255) * 32 + e4]);

        if (p.x >> 8) { v0.x += went.x; v0.y += went.y; v0.z += went.z; v0.w += went.w; }
        if (p.y >> 8) { v1.x += went.x; v1.y += went.y; v1.z += went.z; v1.w += went.w; }
        if (p.z >> 8) { v2.x += went.x; v2.y += went.y; v2.z += went.z; v2.w += went.w; }
        if (p.w >> 8) { v3.x += went.x; v3.y += went.y; v3.z += went.z; v3.w += went.w; }

        float4* __restrict__ base = (float4*)(out_i + (size_t)jb * 4 * 128);
        __stcs(base + 0 * 32 + e4, v0);
        __stcs(base + 1 * 32 + e4, v1);
        __stcs(base + 2 * 32 + e4, v2);
        __stcs(base + 3 * 32 + e4, v3);
    }
}

extern "C" void kernel_launch(void* const* d_in, const int* in_sizes, int n_in,
                              void* d_out, int out_size)
{
    const float* feats = (const float*)d_in[0];   // [1, n, 10] f32
    const float* W     = (const float*)d_in[1];   // [139, 128] f32
    float* out         = (float*)d_out;           // [1, n, n, 128] f32

    const int n = in_sizes[0] / 10;               // b == 1 (n == 1024)

    build_table<<<(TAB_ROWS * 128 + 255) / 256, 256>>>(W);
    rpe_main<<<n, 128>>>(feats, out, n);
}

// round 7
// speedup vs baseline: 1.3554x; 1.3554x over previous
#include <cuda_runtime.h>
#include <cuda_bf16.h>
#include <cstdint>

// Folded table in GLOBAL memory (i-independent, built once by a pre-kernel):
//   rows   0..4  : C[c] = W[65] + W[131] + W[133+c]   (diff chain, HOT: ~98.4% of pairs)
//   row    5     : W[132]                             (entity row)
//   rows   6..70 : A[r] = W[r] + W[131] + W[138]      (same chain, dres!=0)
//   rows  71..135: B[t] = W[32] + W[66+t] + W[138]    (same chain, dres==0)
// Main kernel: 256 thr (8 warps), <=7 blocks/SM (grid 1024 on 148 SMs -> single
// wave). Warp handles 4 consecutive j rows per iteration: one int4 LDS broadcast,
// 4 LDG.128 table reads (L1-hot), 4 STG.128 streaming stores over a 2KB span.

#define TAB_ROWS 136

__device__ float g_table[TAB_ROWS * 128];

__global__ void build_table(const float* __restrict__ W)
{
    const int idx = blockIdx.x * blockDim.x + threadIdx.x;
    if (idx >= TAB_ROWS * 128) return;
    const int r = idx >> 7;
    const int e = idx & 127;
    float v;
    if (r < 5) {
        v = W[65 * 128 + e] + W[131 * 128 + e] + W[(133 + r) * 128 + e];
    } else if (r == 5) {
        v = W[132 * 128 + e];
    } else if (r < 71) {
        v = W[(r - 6) * 128 + e] + W[131 * 128 + e] + W[138 * 128 + e];
    } else {
        v = W[32 * 128 + e] + W[(66 + (r - 71)) * 128 + e] + W[138 * 128 + e];
    }
    g_table[idx] = v;
}

__global__ void __launch_bounds__(256, 7)
rpe_main(const float* __restrict__ feats, float* __restrict__ out, int n)
{
    __shared__ int jidx[1024];

    const int tid = threadIdx.x;
    const int i   = blockIdx.x;

    // ---- Phase A: per-j packed index (row | ent<<8) ----
    const float res_i  = feats[i * 10 + 0];
    const float tok_i  = feats[i * 10 + 1];
    const float asym_i = feats[i * 10 + 2];
    const float ent_i  = feats[i * 10 + 3];
    const float sym_i  = feats[i * 10 + 4];

    for (int j = tid; j < n; j += blockDim.x) {
        const float res_j  = feats[j * 10 + 0];
        const float tok_j  = feats[j * 10 + 1];
        const float asym_j = feats[j * 10 + 2];
        const float ent_j  = feats[j * 10 + 3];
        const float sym_j  = feats[j * 10 + 4];

        int row;
        if (asym_i == asym_j) {
            const int dres = (int)(res_i - res_j);
            if (dres != 0) {
                row = 6 + min(max(dres + 32, 0), 64);          // A table
            } else {
                const int dtok = (int)(tok_i - tok_j);
                row = 71 + min(max(dtok + 32, 0), 64);         // B table
            }
        } else {
            row = min(max((int)(sym_i - sym_j) + 2, 0), 4);    // C table (hot)
        }
        const int ent = (ent_i == ent_j) ? 1 : 0;
        jidx[j] = row | (ent << 8);
    }
    __syncthreads();

    // ---- Phase B: 4 consecutive j rows per warp-iteration, 8 warps ----
    const int e4  = tid & 31;                    // float4 lane within 128-dim row
    const int wid = tid >> 5;                    // 8 warps
    const float4* __restrict__ T4 = (const float4*)g_table;
    const int4*   __restrict__ J4 = (const int4*)jidx;

    const float4 went = __ldg(&T4[5 * 32 + e4]); // entity row in registers

    const int nb4 = n >> 2;                      // 256 groups of 4 j's
    // per-warp running output pointer: one IADD per iter instead of full addressing
    float4* __restrict__ base =
        (float4*)(out + ((size_t)i * (size_t)n) * 128) + (size_t)wid * 128 + e4;
    const size_t step = (size_t)8 * 128;         // 8 warps * 4 rows * 32 float4

    for (int jb = wid; jb < nb4; jb += 8, base += step) {
        const int4 p = J4[jb];                   // one LDS.128 broadcast = 4 indices

        float4 v0 = __ldg(&T4[(p.x & 255) * 32 + e4]);
        float4 v1 = __ldg(&T4[(p.y & 255) * 32 + e4]);
        float4 v2 = __ldg(&T4[(p.z & 255) * 32 + e4]);
        float4 v3 = __ldg(&T4[(p.w & 255) * 32 + e4]);

        if (p.x >> 8) { v0.x += went.x; v0.y += went.y; v0.z += went.z; v0.w += went.w; }
        if (p.y >> 8) { v1.x += went.x; v1.y += went.y; v1.z += went.z; v1.w += went.w; }
        if (p.z >> 8) { v2.x += went.x; v2.y += went.y; v2.z += went.z; v2.w += went.w; }
        if (p.w >> 8) { v3.x += went.x; v3.y += went.y; v3.z += went.z; v3.w += went.w; }

        __stcs(base + 0 * 32, v0);
        __stcs(base + 1 * 32, v1);
        __stcs(base + 2 * 32, v2);
        __stcs(base + 3 * 32, v3);
    }
}

extern "C" void kernel_launch(void* const* d_in, const int* in_sizes, int n_in,
                              void* d_out, int out_size)
{
    const float* feats = (const float*)d_in[0];   // [1, n, 10] f32
    const float* W     = (const float*)d_in[1];   // [139, 128] f32
    float* out         = (float*)d_out;           // [1, n, n, 128] f32

    const int n = in_sizes[0] / 10;               // b == 1 (n == 1024)

    build_table<<<(TAB_ROWS * 128 + 255) / 256, 256>>>(W);
    rpe_main<<<n, 256>>>(feats, out, n);
}